// round 9
// baseline (speedup 1.0000x reference)
#include <cuda_runtime.h>
#include <cuda_fp16.h>
#include <cstdint>

#define B_   4
#define CK   64
#define NN   4032
#define MM   4032
#define NP   4096
#define KH   192            // fp16 split K: A=[hi|lo|hi], B=[hi|hi|lo]
#define SPITCH 400          // smem row pitch in BYTES (odd multiple of 16B)

// ---- device scratch (allocation-free rule) ----
__device__ __align__(16) __half g_hA[(size_t)B_ * NP * KH];   // mk split, K-major
__device__ __align__(16) __half g_hB[(size_t)B_ * NP * KH];   // qk split, K-major
__device__ __align__(16) __half g_S [(size_t)B_ * NP * NP];   // unnormalized p (fp16)
__device__ float g_msq8  [B_ * NP];   // ||mk_n||^2 / 8
__device__ float g_colsum[B_ * NP];   // colsum per (b, m)
__device__ int   g_cnt   [B_ * 32];   // completed n-tiles per (b, m-strip)

__device__ __forceinline__ uint32_t smem_u32(const void* p) {
    return (uint32_t)__cvta_generic_to_shared(p);
}
__device__ __forceinline__ void ldsm_x4(uint32_t& r0, uint32_t& r1,
                                        uint32_t& r2, uint32_t& r3, uint32_t a) {
    asm volatile("ldmatrix.sync.aligned.m8n8.x4.shared.b16 {%0,%1,%2,%3}, [%4];"
                 : "=r"(r0), "=r"(r1), "=r"(r2), "=r"(r3) : "r"(a));
}
__device__ __forceinline__ void mma16816(float* d, const uint32_t* a,
                                         uint32_t b0, uint32_t b1) {
    asm volatile("mma.sync.aligned.m16n8k16.row.col.f32.f16.f16.f32 "
                 "{%0,%1,%2,%3}, {%4,%5,%6,%7}, {%8,%9}, {%0,%1,%2,%3};"
                 : "+f"(d[0]), "+f"(d[1]), "+f"(d[2]), "+f"(d[3])
                 : "r"(a[0]), "r"(a[1]), "r"(a[2]), "r"(a[3]), "r"(b0), "r"(b1));
}
__device__ __forceinline__ void cp16(uint32_t dst, const void* src) {
    asm volatile("cp.async.cg.shared.global [%0], [%1], 16;"
                 :: "r"(dst), "l"(src) : "memory");
}

// ---------------------------------------------------------------------------
// Convert: fp32 -> fp16 hi/lo split, K-major padded scratch; msq/8; zero
// colsum + strip counters (re-zeroed every launch for graph replays).
// grid (NP/128, B_, 2): z=0 mk->g_hA (hi|lo|hi), z=1 qk->g_hB (hi|hi|lo).
// ---------------------------------------------------------------------------
__global__ __launch_bounds__(256) void conv_kernel(const float* __restrict__ mk,
                                                   const float* __restrict__ qk) {
    __shared__ float s[64][129];
    const int z = blockIdx.z, b = blockIdx.y, n0 = blockIdx.x * 128;
    const int tid = threadIdx.x;
    const float* src = (z ? qk : mk) + (size_t)b * CK * NN;

    if (z == 0 && tid == 0) g_cnt[b * 32 + blockIdx.x] = 0;

    for (int idx = tid; idx < 64 * 128; idx += 256) {
        int c = idx >> 7, n = idx & 127;
        s[c][n] = (n0 + n < NN) ? src[(size_t)c * NN + n0 + n] : 0.f;
    }
    __syncthreads();

    if (z == 0 && tid < 128) {
        float acc = 0.f;
        #pragma unroll
        for (int c = 0; c < 64; ++c) acc += s[c][tid] * s[c][tid];
        g_msq8  [b * NP + n0 + tid] = 0.125f * acc;
        g_colsum[b * NP + n0 + tid] = 0.f;
    }

    __half2* dst = (__half2*)((z ? g_hB : g_hA) + ((size_t)b * NP + n0) * KH);
    for (int idx = tid; idx < 128 * 96; idx += 256) {
        int n = idx / 96, w = idx - n * 96;
        int seg = w >> 5;                 // 0,1,2 (64 halves each)
        int c = (2 * w) & 63;             // channel within segment
        bool want_lo = z ? (seg == 2) : (seg == 1);
        float x0 = s[c][n], x1 = s[c + 1][n];
        __half h0 = __float2half_rn(x0), h1 = __float2half_rn(x1);
        if (want_lo) {
            h0 = __float2half_rn(x0 - __half2float(h0));
            h1 = __float2half_rn(x1 - __half2float(h1));
        }
        dst[(size_t)n * 96 + w] = __halves2half2(h0, h1);
    }
}

// ---------------------------------------------------------------------------
// Fused GEMM + exp + colsum + (last CTA per m-strip) normalization.
// Grid (32 n-tiles FAST, 32 m-strips, B_): consecutive bids cover one strip,
// so strips complete early and their normalization overlaps remaining GEMM.
// ---------------------------------------------------------------------------
#define SM_A 0
#define SM_B 51200
#define SMEM_P1 102400

__global__ __launch_bounds__(256, 2) void gemm_fused(float* __restrict__ out) {
    extern __shared__ __align__(16) char smem[];
    __shared__ float colred[128];
    __shared__ int s_last;
    const int tid = threadIdx.x;
    const int n0 = blockIdx.x * 128;      // n-tile (fast dim)
    const int m0 = blockIdx.y * 128;      // m-strip
    const int b  = blockIdx.z;
    const int w = tid >> 5, lane = tid & 31;
    const int wm = w & 3, wn = w >> 2;
    const uint32_t sbase = smem_u32(smem);

    if (tid < 128) colred[tid] = 0.f;

    // Issue all operand loads: 3 chunks x (A 1024 + B 1024) 16B cp.async ops.
    {
        const uint4* gA = (const uint4*)(g_hA + ((size_t)b * NP + n0) * KH);
        const uint4* gB = (const uint4*)(g_hB + ((size_t)b * NP + m0) * KH);
        const int r = tid >> 3, j = tid & 7;           // r:0..31, j:0..7
        #pragma unroll
        for (int c = 0; c < 3; ++c) {
            #pragma unroll
            for (int i = 0; i < 4; ++i) {              // rows r, r+32, r+64, r+96
                int rr = r + i * 32;
                int jj = 8 * c + j;                    // uint4 index within row
                cp16(sbase + SM_A + rr * SPITCH + jj * 16, gA + (size_t)rr * 24 + jj);
                cp16(sbase + SM_B + rr * SPITCH + jj * 16, gB + (size_t)rr * 24 + jj);
            }
            asm volatile("cp.async.commit_group;" ::: "memory");
        }
    }

    float d[2][8][4];
    #pragma unroll
    for (int i = 0; i < 2; ++i)
        #pragma unroll
        for (int j = 0; j < 8; ++j)
            #pragma unroll
            for (int k = 0; k < 4; ++k) d[i][j][k] = 0.f;

    // ldmatrix lane base addresses (pitch 400B -> conflict-free 8-row groups)
    const uint32_t aAddr = sbase + SM_A +
        (wm * 32 + (lane & 15)) * SPITCH + ((lane >> 4) << 4);
    const uint32_t bAddr = sbase + SM_B +
        (wn * 64 + (lane & 7) + ((lane >> 4) << 3)) * SPITCH + (((lane >> 3) & 1) << 4);

    #pragma unroll
    for (int c = 0; c < 3; ++c) {
        if (c == 0)      asm volatile("cp.async.wait_group 2;" ::: "memory");
        else if (c == 1) asm volatile("cp.async.wait_group 1;" ::: "memory");
        else             asm volatile("cp.async.wait_group 0;" ::: "memory");
        __syncthreads();

        #pragma unroll
        for (int k4 = 0; k4 < 4; ++k4) {
            const int kb = (c * 4 + k4) * 32;          // byte offset within row
            uint32_t a[2][4], bf[4][4];
            #pragma unroll
            for (int mi = 0; mi < 2; ++mi)
                ldsm_x4(a[mi][0], a[mi][1], a[mi][2], a[mi][3],
                        aAddr + kb + mi * 16 * SPITCH);
            #pragma unroll
            for (int p = 0; p < 4; ++p)
                ldsm_x4(bf[p][0], bf[p][1], bf[p][2], bf[p][3],
                        bAddr + kb + p * 16 * SPITCH);
            #pragma unroll
            for (int mi = 0; mi < 2; ++mi)
                #pragma unroll
                for (int p = 0; p < 4; ++p) {
                    mma16816(d[mi][2 * p],     a[mi], bf[p][0], bf[p][1]);
                    mma16816(d[mi][2 * p + 1], a[mi], bf[p][2], bf[p][3]);
                }
        }
    }

    // ---- epilogue: exp, store p (fp16), column sums ----
    const int g = lane >> 2, t4 = lane & 3;
    float q[2][2]; bool v[2][2];
    #pragma unroll
    for (int mi = 0; mi < 2; ++mi) {
        int r0 = n0 + wm * 32 + mi * 16 + g;
        q[mi][0] = g_msq8[b * NP + r0];
        q[mi][1] = g_msq8[b * NP + r0 + 8];
        v[mi][0] = r0 < NN; v[mi][1] = r0 + 8 < NN;
    }
    const size_t sb = (size_t)b * NP * NP;

    #pragma unroll
    for (int nj = 0; nj < 8; ++nj) {
        float cs0 = 0.f, cs1 = 0.f;
        const int mcol = m0 + wn * 64 + nj * 8 + 2 * t4;
        #pragma unroll
        for (int mi = 0; mi < 2; ++mi) {
            int r0 = n0 + wm * 32 + mi * 16 + g;
            float p00 = __expf(d[mi][nj][0] * 0.25f - q[mi][0]);
            float p01 = __expf(d[mi][nj][1] * 0.25f - q[mi][0]);
            float p10 = __expf(d[mi][nj][2] * 0.25f - q[mi][1]);
            float p11 = __expf(d[mi][nj][3] * 0.25f - q[mi][1]);
            *(__half2*)(g_S + sb + (size_t)r0 * NP + mcol)       = __floats2half2_rn(p00, p01);
            *(__half2*)(g_S + sb + (size_t)(r0 + 8) * NP + mcol) = __floats2half2_rn(p10, p11);
            if (v[mi][0]) { cs0 += p00; cs1 += p01; }
            if (v[mi][1]) { cs0 += p10; cs1 += p11; }
        }
        #pragma unroll
        for (int off = 4; off <= 16; off <<= 1) {
            cs0 += __shfl_xor_sync(0xffffffffu, cs0, off);
            cs1 += __shfl_xor_sync(0xffffffffu, cs1, off);
        }
        if (g == 0) {
            atomicAdd(&colred[wn * 64 + nj * 8 + 2 * t4],     cs0);
            atomicAdd(&colred[wn * 64 + nj * 8 + 2 * t4 + 1], cs1);
        }
    }
    __syncthreads();
    if (tid < 128)
        atomicAdd(&g_colsum[b * NP + m0 + tid], colred[tid]);

    // ---- strip completion: last CTA of this (b, m-strip) normalizes it ----
    __threadfence();                     // release: p tile + colsum visible
    __syncthreads();                     // all threads' fences precede atomic
    if (tid == 0)
        s_last = atomicAdd(&g_cnt[b * 32 + blockIdx.y], 1);
    __syncthreads();
    if (s_last != 31) return;

    __threadfence();                     // acquire side
    if (tid < 128)
        colred[tid] = __frcp_rn(__ldcg(&g_colsum[b * NP + m0 + tid]));
    __syncthreads();

    // Normalize strip: rows 0..NN-1, cols m0..m0+127 (clip to MM).
    const int col = (tid & 15) * 8;      // 8 fp16 cols per thread
    if (m0 + col < MM) {
        float inv[8];
        #pragma unroll
        for (int j = 0; j < 8; ++j) inv[j] = colred[col + j];
        const __half* srow = g_S + sb + m0 + col;
        float* orow = out + ((size_t)b * NN) * MM + m0 + col;
        for (int n = tid >> 4; n < NN; n += 16) {
            uint4 hv = __ldcg((const uint4*)(srow + (size_t)n * NP));
            const __half2* h2 = (const __half2*)&hv;
            float2 f0 = __half22float2(h2[0]), f1 = __half22float2(h2[1]);
            float2 f2 = __half22float2(h2[2]), f3 = __half22float2(h2[3]);
            float* o = orow + (size_t)n * MM;
            *(float4*)o       = make_float4(f0.x * inv[0], f0.y * inv[1],
                                            f1.x * inv[2], f1.y * inv[3]);
            *(float4*)(o + 4) = make_float4(f2.x * inv[4], f2.y * inv[5],
                                            f3.x * inv[6], f3.y * inv[7]);
        }
    }
}

// ---------------------------------------------------------------------------
extern "C" void kernel_launch(void* const* d_in, const int* in_sizes, int n_in,
                              void* d_out, int out_size) {
    const float* mk = (const float*)d_in[0];
    const float* qk = (const float*)d_in[1];
    float* out = (float*)d_out;

    cudaFuncSetAttribute(gemm_fused,
                         cudaFuncAttributeMaxDynamicSharedMemorySize, SMEM_P1);

    dim3 cg(NP / 128, B_, 2);
    conv_kernel<<<cg, 256>>>(mk, qk);

    dim3 gg(32, 32, B_);                 // x = n-tile (fast), y = m-strip, z = b
    gemm_fused<<<gg, 256, SMEM_P1>>>(out);
}

// round 10
// speedup vs baseline: 1.4143x; 1.4143x over previous
#include <cuda_runtime.h>
#include <cuda_fp16.h>
#include <cstdint>

#define B_   4
#define CK   64
#define NN   4032
#define MM   4032
#define NP   4096
#define KH   192            // fp16 split K: A=[hi|lo|hi], B=[hi|hi|lo]
#define SPITCH 400          // smem row pitch in BYTES (odd multiple of 16B)
#define NTILES 4096         // gemm tiles (and norm tiles)
#define LAG   640           // gemm items before norm items interleave
#define NROWS 126           // rows per norm tile (32*126 = 4032)

// ---- device scratch (allocation-free rule) ----
__device__ __align__(16) __half g_hA[(size_t)B_ * NP * KH];   // mk split, K-major
__device__ __align__(16) __half g_hB[(size_t)B_ * NP * KH];   // qk split, K-major
__device__ __align__(16) __half g_S [(size_t)B_ * NP * NP];   // unnormalized p (fp16)
__device__ float g_msq8  [B_ * NP];   // ||mk_n||^2 / 8
__device__ float g_colsum[B_ * NP];   // colsum per (b, m)
__device__ int   g_cnt   [B_ * 32];   // completed n-tiles per (b, m-strip)
__device__ int   g_work;              // work-queue counter

__device__ __forceinline__ uint32_t smem_u32(const void* p) {
    return (uint32_t)__cvta_generic_to_shared(p);
}
__device__ __forceinline__ void ldsm_x4(uint32_t& r0, uint32_t& r1,
                                        uint32_t& r2, uint32_t& r3, uint32_t a) {
    asm volatile("ldmatrix.sync.aligned.m8n8.x4.shared.b16 {%0,%1,%2,%3}, [%4];"
                 : "=r"(r0), "=r"(r1), "=r"(r2), "=r"(r3) : "r"(a));
}
__device__ __forceinline__ void mma16816(float* d, const uint32_t* a,
                                         uint32_t b0, uint32_t b1) {
    asm volatile("mma.sync.aligned.m16n8k16.row.col.f32.f16.f16.f32 "
                 "{%0,%1,%2,%3}, {%4,%5,%6,%7}, {%8,%9}, {%0,%1,%2,%3};"
                 : "+f"(d[0]), "+f"(d[1]), "+f"(d[2]), "+f"(d[3])
                 : "r"(a[0]), "r"(a[1]), "r"(a[2]), "r"(a[3]), "r"(b0), "r"(b1));
}
__device__ __forceinline__ void cp16(uint32_t dst, const void* src) {
    asm volatile("cp.async.cg.shared.global [%0], [%1], 16;"
                 :: "r"(dst), "l"(src) : "memory");
}

// ---------------------------------------------------------------------------
// Convert: fp32 -> fp16 hi/lo split, K-major padded scratch; msq/8; zero
// colsum + counters (re-zeroed every launch for graph replays).
// ---------------------------------------------------------------------------
__global__ __launch_bounds__(256) void conv_kernel(const float* __restrict__ mk,
                                                   const float* __restrict__ qk) {
    __shared__ float s[64][129];
    const int z = blockIdx.z, b = blockIdx.y, n0 = blockIdx.x * 128;
    const int tid = threadIdx.x;
    const float* src = (z ? qk : mk) + (size_t)b * CK * NN;

    if (z == 0 && tid == 0) {
        g_cnt[b * 32 + blockIdx.x] = 0;
        if (b == 0 && blockIdx.x == 0) g_work = 0;
    }

    for (int idx = tid; idx < 64 * 128; idx += 256) {
        int c = idx >> 7, n = idx & 127;
        s[c][n] = (n0 + n < NN) ? src[(size_t)c * NN + n0 + n] : 0.f;
    }
    __syncthreads();

    if (z == 0 && tid < 128) {
        float acc = 0.f;
        #pragma unroll
        for (int c = 0; c < 64; ++c) acc += s[c][tid] * s[c][tid];
        g_msq8  [b * NP + n0 + tid] = 0.125f * acc;
        g_colsum[b * NP + n0 + tid] = 0.f;
    }

    __half2* dst = (__half2*)((z ? g_hB : g_hA) + ((size_t)b * NP + n0) * KH);
    for (int idx = tid; idx < 128 * 96; idx += 256) {
        int n = idx / 96, w = idx - n * 96;
        int seg = w >> 5;
        int c = (2 * w) & 63;
        bool want_lo = z ? (seg == 2) : (seg == 1);
        float x0 = s[c][n], x1 = s[c + 1][n];
        __half h0 = __float2half_rn(x0), h1 = __float2half_rn(x1);
        if (want_lo) {
            h0 = __float2half_rn(x0 - __half2float(h0));
            h1 = __float2half_rn(x1 - __half2float(h1));
        }
        dst[(size_t)n * 96 + w] = __halves2half2(h0, h1);
    }
}

// ---------------------------------------------------------------------------
// Persistent fused kernel: dual work queue (gemm tiles + norm tiles).
// ---------------------------------------------------------------------------
#define SM_A 0
#define SM_B 51200
#define SMEM_P1 102400

struct SmemShared { float colred[128]; int idx; };

// ---- one 128x128 GEMM tile: mma + exp + p-store + colsum + strip counter ----
__device__ __forceinline__ void do_gemm_tile(char* smem, SmemShared* sh,
                                             int t, int tid) {
    const int st = t >> 5;                 // global strip id
    const int b  = st >> 5;
    const int m0 = (st & 31) * 128;
    const int n0 = (t & 31) * 128;
    const int w = tid >> 5, lane = tid & 31;
    const int wm = w & 3, wn = w >> 2;
    const uint32_t sbase = smem_u32(smem);

    if (tid < 128) sh->colred[tid] = 0.f;

    {
        const uint4* gA = (const uint4*)(g_hA + ((size_t)b * NP + n0) * KH);
        const uint4* gB = (const uint4*)(g_hB + ((size_t)b * NP + m0) * KH);
        const int r = tid >> 3, j = tid & 7;
        #pragma unroll
        for (int c = 0; c < 3; ++c) {
            #pragma unroll
            for (int i = 0; i < 4; ++i) {
                int rr = r + i * 32;
                int jj = 8 * c + j;
                cp16(sbase + SM_A + rr * SPITCH + jj * 16, gA + (size_t)rr * 24 + jj);
                cp16(sbase + SM_B + rr * SPITCH + jj * 16, gB + (size_t)rr * 24 + jj);
            }
            asm volatile("cp.async.commit_group;" ::: "memory");
        }
    }

    float d[2][8][4];
    #pragma unroll
    for (int i = 0; i < 2; ++i)
        #pragma unroll
        for (int j = 0; j < 8; ++j)
            #pragma unroll
            for (int k = 0; k < 4; ++k) d[i][j][k] = 0.f;

    const uint32_t aAddr = sbase + SM_A +
        (wm * 32 + (lane & 15)) * SPITCH + ((lane >> 4) << 4);
    const uint32_t bAddr = sbase + SM_B +
        (wn * 64 + (lane & 7) + ((lane >> 4) << 3)) * SPITCH + (((lane >> 3) & 1) << 4);

    #pragma unroll
    for (int c = 0; c < 3; ++c) {
        if (c == 0)      asm volatile("cp.async.wait_group 2;" ::: "memory");
        else if (c == 1) asm volatile("cp.async.wait_group 1;" ::: "memory");
        else             asm volatile("cp.async.wait_group 0;" ::: "memory");
        __syncthreads();

        #pragma unroll
        for (int k4 = 0; k4 < 4; ++k4) {
            const int kb = (c * 4 + k4) * 32;
            uint32_t a[2][4], bf[4][4];
            #pragma unroll
            for (int mi = 0; mi < 2; ++mi)
                ldsm_x4(a[mi][0], a[mi][1], a[mi][2], a[mi][3],
                        aAddr + kb + mi * 16 * SPITCH);
            #pragma unroll
            for (int p = 0; p < 4; ++p)
                ldsm_x4(bf[p][0], bf[p][1], bf[p][2], bf[p][3],
                        bAddr + kb + p * 16 * SPITCH);
            #pragma unroll
            for (int mi = 0; mi < 2; ++mi)
                #pragma unroll
                for (int p = 0; p < 4; ++p) {
                    mma16816(d[mi][2 * p],     a[mi], bf[p][0], bf[p][1]);
                    mma16816(d[mi][2 * p + 1], a[mi], bf[p][2], bf[p][3]);
                }
        }
    }

    // Epilogue: exp, p-store (plain: keep in L2 for norm), colsum
    const int g = lane >> 2, t4 = lane & 3;
    float q[2][2]; bool v[2][2];
    #pragma unroll
    for (int mi = 0; mi < 2; ++mi) {
        int r0 = n0 + wm * 32 + mi * 16 + g;
        q[mi][0] = g_msq8[b * NP + r0];
        q[mi][1] = g_msq8[b * NP + r0 + 8];
        v[mi][0] = r0 < NN; v[mi][1] = r0 + 8 < NN;
    }
    const size_t sb = (size_t)b * NP * NP;

    #pragma unroll
    for (int nj = 0; nj < 8; ++nj) {
        float cs0 = 0.f, cs1 = 0.f;
        const int mcol = m0 + wn * 64 + nj * 8 + 2 * t4;
        #pragma unroll
        for (int mi = 0; mi < 2; ++mi) {
            int r0 = n0 + wm * 32 + mi * 16 + g;
            float p00 = __expf(d[mi][nj][0] * 0.25f - q[mi][0]);
            float p01 = __expf(d[mi][nj][1] * 0.25f - q[mi][0]);
            float p10 = __expf(d[mi][nj][2] * 0.25f - q[mi][1]);
            float p11 = __expf(d[mi][nj][3] * 0.25f - q[mi][1]);
            *(__half2*)(g_S + sb + (size_t)r0 * NP + mcol)       = __floats2half2_rn(p00, p01);
            *(__half2*)(g_S + sb + (size_t)(r0 + 8) * NP + mcol) = __floats2half2_rn(p10, p11);
            if (v[mi][0]) { cs0 += p00; cs1 += p01; }
            if (v[mi][1]) { cs0 += p10; cs1 += p11; }
        }
        #pragma unroll
        for (int off = 4; off <= 16; off <<= 1) {
            cs0 += __shfl_xor_sync(0xffffffffu, cs0, off);
            cs1 += __shfl_xor_sync(0xffffffffu, cs1, off);
        }
        if (g == 0) {
            atomicAdd(&sh->colred[wn * 64 + nj * 8 + 2 * t4],     cs0);
            atomicAdd(&sh->colred[wn * 64 + nj * 8 + 2 * t4 + 1], cs1);
        }
    }
    __syncthreads();
    if (tid < 128)
        atomicAdd(&g_colsum[b * NP + m0 + tid], sh->colred[tid]);

    __threadfence();                       // release p-tile + colsum
    __syncthreads();
    if (tid == 0)
        atomicAdd(&g_cnt[st], 1);
}

// ---- one 126x128 norm tile: wait strip, read p, scale, write out ----
__device__ __forceinline__ void do_norm_tile(SmemShared* sh, float* __restrict__ out,
                                             int u, int tid) {
    const int su = u >> 5;                 // strip id
    const int b  = su >> 5;
    const int m0 = (su & 31) * 128;
    const int nbase = (u & 31) * NROWS;

    if (tid == 0) {
        while (*(volatile int*)&g_cnt[su] != 32) __nanosleep(100);
    }
    __syncthreads();
    __threadfence();                       // acquire

    if (tid < 128)
        sh->colred[tid] = __frcp_rn(__ldcg(&g_colsum[b * NP + m0 + tid]));
    __syncthreads();

    const int col = (tid & 15) * 8;
    if (m0 + col < MM) {
        float inv[8];
        #pragma unroll
        for (int j = 0; j < 8; ++j) inv[j] = sh->colred[col + j];
        const size_t sb = (size_t)b * NP * NP;
        const __half* srow = g_S + sb + m0 + col;
        float* orow = out + (size_t)b * NN * MM + m0 + col;
        for (int nl = tid >> 4; nl < NROWS; nl += 16) {
            int n = nbase + nl;
            uint4 hv = __ldcg((const uint4*)(srow + (size_t)n * NP));
            const __half2* h2 = (const __half2*)&hv;
            float2 f0 = __half22float2(h2[0]), f1 = __half22float2(h2[1]);
            float2 f2 = __half22float2(h2[2]), f3 = __half22float2(h2[3]);
            float* o = orow + (size_t)n * MM;
            __stcs((float4*)o,       make_float4(f0.x * inv[0], f0.y * inv[1],
                                                 f1.x * inv[2], f1.y * inv[3]));
            __stcs((float4*)(o + 4), make_float4(f2.x * inv[4], f2.y * inv[5],
                                                 f3.x * inv[6], f3.y * inv[7]));
        }
    }
}

__global__ __launch_bounds__(256, 2) void fused_persist(float* __restrict__ out) {
    extern __shared__ __align__(16) char smem[];
    __shared__ SmemShared sh;
    const int tid = threadIdx.x;

    for (;;) {
        if (tid == 0) sh.idx = atomicAdd(&g_work, 1);
        __syncthreads();
        const int idx = sh.idx;
        if (idx >= 2 * NTILES) break;

        int type, tile;                    // 0 = gemm, 1 = norm
        if (idx < LAG) { type = 0; tile = idx; }
        else if (idx < LAG + 2 * (NTILES - LAG)) {
            int rel = idx - LAG;
            if ((rel & 1) == 0) { type = 0; tile = LAG + (rel >> 1); }
            else                { type = 1; tile = rel >> 1; }
        } else {
            type = 1; tile = (NTILES - LAG) + (idx - (LAG + 2 * (NTILES - LAG)));
        }

        if (type == 0) do_gemm_tile(smem, &sh, tile, tid);
        else           do_norm_tile(&sh, out, tile, tid);
        __syncthreads();                   // protect smem reuse across items
    }
}

// ---------------------------------------------------------------------------
extern "C" void kernel_launch(void* const* d_in, const int* in_sizes, int n_in,
                              void* d_out, int out_size) {
    const float* mk = (const float*)d_in[0];
    const float* qk = (const float*)d_in[1];
    float* out = (float*)d_out;

    cudaFuncSetAttribute(fused_persist,
                         cudaFuncAttributeMaxDynamicSharedMemorySize, SMEM_P1);

    dim3 cg(NP / 128, B_, 2);
    conv_kernel<<<cg, 256>>>(mk, qk);

    fused_persist<<<296, 256, SMEM_P1>>>(out);   // 148 SMs x 2 CTAs
}

// round 13
// speedup vs baseline: 1.4674x; 1.0375x over previous
#include <cuda_runtime.h>
#include <cuda_fp16.h>
#include <cstdint>

#define B_   4
#define CK   64
#define NN   4032
#define MM   4032
#define NP   4096
#define KH   192            // fp16 split K: A=[hi|lo|hi], B=[hi|hi|lo]
#define SPITCH 400          // smem row pitch in BYTES (odd multiple of 16B)

// ---- device scratch (allocation-free rule) ----
__device__ __align__(16) __half g_hA[(size_t)B_ * NP * KH];   // mk split, K-major
__device__ __align__(16) __half g_hB[(size_t)B_ * NP * KH];   // qk split, K-major
__device__ __align__(16) __half g_S [(size_t)B_ * NP * NP];   // unnormalized p (fp16)
__device__ float g_msq8  [B_ * NP];   // ||mk_n||^2 / 8
__device__ float g_colsum[B_ * NP];   // colsum -> inverted in place (per batch)

__device__ __forceinline__ uint32_t smem_u32(const void* p) {
    return (uint32_t)__cvta_generic_to_shared(p);
}
__device__ __forceinline__ void ldsm_x4(uint32_t& r0, uint32_t& r1,
                                        uint32_t& r2, uint32_t& r3, uint32_t a) {
    asm volatile("ldmatrix.sync.aligned.m8n8.x4.shared.b16 {%0,%1,%2,%3}, [%4];"
                 : "=r"(r0), "=r"(r1), "=r"(r2), "=r"(r3) : "r"(a));
}
__device__ __forceinline__ void mma16816(float* d, const uint32_t* a,
                                         uint32_t b0, uint32_t b1) {
    asm volatile("mma.sync.aligned.m16n8k16.row.col.f32.f16.f16.f32 "
                 "{%0,%1,%2,%3}, {%4,%5,%6,%7}, {%8,%9}, {%0,%1,%2,%3};"
                 : "+f"(d[0]), "+f"(d[1]), "+f"(d[2]), "+f"(d[3])
                 : "r"(a[0]), "r"(a[1]), "r"(a[2]), "r"(a[3]), "r"(b0), "r"(b1));
}
__device__ __forceinline__ void cp16(uint32_t dst, const void* src) {
    asm volatile("cp.async.cg.shared.global [%0], [%1], 16;"
                 :: "r"(dst), "l"(src) : "memory");
}

// ---------------------------------------------------------------------------
// Convert: fp32 -> fp16 hi/lo split, K-major padded scratch; msq/8; zero colsum.
// grid (NP/128, B_, 2): z=0 mk->g_hA (hi|lo|hi), z=1 qk->g_hB (hi|hi|lo).
// ---------------------------------------------------------------------------
__global__ __launch_bounds__(256) void conv_kernel(const float* __restrict__ mk,
                                                   const float* __restrict__ qk) {
    __shared__ float s[64][129];
    const int z = blockIdx.z, b = blockIdx.y, n0 = blockIdx.x * 128;
    const int tid = threadIdx.x;
    const float* src = (z ? qk : mk) + (size_t)b * CK * NN;

    for (int idx = tid; idx < 64 * 128; idx += 256) {
        int c = idx >> 7, n = idx & 127;
        s[c][n] = (n0 + n < NN) ? src[(size_t)c * NN + n0 + n] : 0.f;
    }
    __syncthreads();

    if (z == 0 && tid < 128) {
        float acc = 0.f;
        #pragma unroll
        for (int c = 0; c < 64; ++c) acc += s[c][tid] * s[c][tid];
        g_msq8  [b * NP + n0 + tid] = 0.125f * acc;
        g_colsum[b * NP + n0 + tid] = 0.f;
    }

    __half2* dst = (__half2*)((z ? g_hB : g_hA) + ((size_t)b * NP + n0) * KH);
    for (int idx = tid; idx < 128 * 96; idx += 256) {
        int n = idx / 96, w = idx - n * 96;
        int seg = w >> 5;
        int c = (2 * w) & 63;
        bool want_lo = z ? (seg == 2) : (seg == 1);
        float x0 = s[c][n], x1 = s[c + 1][n];
        __half h0 = __float2half_rn(x0), h1 = __float2half_rn(x1);
        if (want_lo) {
            h0 = __float2half_rn(x0 - __half2float(h0));
            h1 = __float2half_rn(x1 - __half2float(h1));
        }
        dst[(size_t)n * 96 + w] = __halves2half2(h0, h1);
    }
}

// ---------------------------------------------------------------------------
// GEMM (one batch): 128x128 tile over K=192 via mma.sync m16n8k16,
// cp.async-staged operands, fused exp + fp16 p-store + column sums.
// ---------------------------------------------------------------------------
#define SM_A 0
#define SM_B 51200
#define SMEM_P1 102400

__global__ __launch_bounds__(256, 2) void gemm_pass1(int b) {
    extern __shared__ __align__(16) char smem[];
    __shared__ float colred[128];
    const int tid = threadIdx.x;
    const int m0 = blockIdx.x * 128, n0 = blockIdx.y * 128;
    const int w = tid >> 5, lane = tid & 31;
    const int wm = w & 3, wn = w >> 2;
    const uint32_t sbase = smem_u32(smem);

    if (tid < 128) colred[tid] = 0.f;

    {
        const uint4* gA = (const uint4*)(g_hA + ((size_t)b * NP + n0) * KH);
        const uint4* gB = (const uint4*)(g_hB + ((size_t)b * NP + m0) * KH);
        const int r = tid >> 3, j = tid & 7;
        #pragma unroll
        for (int c = 0; c < 3; ++c) {
            #pragma unroll
            for (int i = 0; i < 4; ++i) {
                int rr = r + i * 32;
                int jj = 8 * c + j;
                cp16(sbase + SM_A + rr * SPITCH + jj * 16, gA + (size_t)rr * 24 + jj);
                cp16(sbase + SM_B + rr * SPITCH + jj * 16, gB + (size_t)rr * 24 + jj);
            }
            asm volatile("cp.async.commit_group;" ::: "memory");
        }
    }

    float d[2][8][4];
    #pragma unroll
    for (int i = 0; i < 2; ++i)
        #pragma unroll
        for (int j = 0; j < 8; ++j)
            #pragma unroll
            for (int k = 0; k < 4; ++k) d[i][j][k] = 0.f;

    const uint32_t aAddr = sbase + SM_A +
        (wm * 32 + (lane & 15)) * SPITCH + ((lane >> 4) << 4);
    const uint32_t bAddr = sbase + SM_B +
        (wn * 64 + (lane & 7) + ((lane >> 4) << 3)) * SPITCH + (((lane >> 3) & 1) << 4);

    #pragma unroll
    for (int c = 0; c < 3; ++c) {
        if (c == 0)      asm volatile("cp.async.wait_group 2;" ::: "memory");
        else if (c == 1) asm volatile("cp.async.wait_group 1;" ::: "memory");
        else             asm volatile("cp.async.wait_group 0;" ::: "memory");
        __syncthreads();

        #pragma unroll
        for (int k4 = 0; k4 < 4; ++k4) {
            const int kb = (c * 4 + k4) * 32;
            uint32_t a[2][4], bf[4][4];
            #pragma unroll
            for (int mi = 0; mi < 2; ++mi)
                ldsm_x4(a[mi][0], a[mi][1], a[mi][2], a[mi][3],
                        aAddr + kb + mi * 16 * SPITCH);
            #pragma unroll
            for (int p = 0; p < 4; ++p)
                ldsm_x4(bf[p][0], bf[p][1], bf[p][2], bf[p][3],
                        bAddr + kb + p * 16 * SPITCH);
            #pragma unroll
            for (int mi = 0; mi < 2; ++mi)
                #pragma unroll
                for (int p = 0; p < 4; ++p) {
                    mma16816(d[mi][2 * p],     a[mi], bf[p][0], bf[p][1]);
                    mma16816(d[mi][2 * p + 1], a[mi], bf[p][2], bf[p][3]);
                }
        }
    }

    const int g = lane >> 2, t4 = lane & 3;
    float q[2][2]; bool v[2][2];
    #pragma unroll
    for (int mi = 0; mi < 2; ++mi) {
        int r0 = n0 + wm * 32 + mi * 16 + g;
        q[mi][0] = g_msq8[b * NP + r0];
        q[mi][1] = g_msq8[b * NP + r0 + 8];
        v[mi][0] = r0 < NN; v[mi][1] = r0 + 8 < NN;
    }
    const size_t sb = (size_t)b * NP * NP;

    #pragma unroll
    for (int nj = 0; nj < 8; ++nj) {
        float cs0 = 0.f, cs1 = 0.f;
        const int mcol = m0 + wn * 64 + nj * 8 + 2 * t4;
        #pragma unroll
        for (int mi = 0; mi < 2; ++mi) {
            int r0 = n0 + wm * 32 + mi * 16 + g;
            float p00 = __expf(d[mi][nj][0] * 0.25f - q[mi][0]);
            float p01 = __expf(d[mi][nj][1] * 0.25f - q[mi][0]);
            float p10 = __expf(d[mi][nj][2] * 0.25f - q[mi][1]);
            float p11 = __expf(d[mi][nj][3] * 0.25f - q[mi][1]);
            *(__half2*)(g_S + sb + (size_t)r0 * NP + mcol)       = __floats2half2_rn(p00, p01);
            *(__half2*)(g_S + sb + (size_t)(r0 + 8) * NP + mcol) = __floats2half2_rn(p10, p11);
            if (v[mi][0]) { cs0 += p00; cs1 += p01; }
            if (v[mi][1]) { cs0 += p10; cs1 += p11; }
        }
        #pragma unroll
        for (int off = 4; off <= 16; off <<= 1) {
            cs0 += __shfl_xor_sync(0xffffffffu, cs0, off);
            cs1 += __shfl_xor_sync(0xffffffffu, cs1, off);
        }
        if (g == 0) {
            atomicAdd(&colred[wn * 64 + nj * 8 + 2 * t4],     cs0);
            atomicAdd(&colred[wn * 64 + nj * 8 + 2 * t4 + 1], cs1);
        }
    }
    __syncthreads();
    if (tid < 128)
        atomicAdd(&g_colsum[b * NP + m0 + tid], colred[tid]);
}

// ---------------------------------------------------------------------------
__global__ void invert_kernel(int b) {
    int i = blockIdx.x * 256 + threadIdx.x;
    if (i < NP) g_colsum[b * NP + i] = __frcp_rn(g_colsum[b * NP + i]);
}

// ---------------------------------------------------------------------------
// Norm (one batch): out = fp16->fp32(g_S) * inv_colsum[b][m].  R6/R8 proven
// shape: 8 cols/thread, plain loads/stores, 7938 blocks per batch.
// ---------------------------------------------------------------------------
__global__ __launch_bounds__(256) void norm_kernel(float* __restrict__ out, int b) {
    size_t idx = (size_t)blockIdx.x * 256 + threadIdx.x;
    const size_t total = (size_t)NN * (NN / 8);
    if (idx >= total) return;
    int mc = (int)(idx % (NN / 8));
    int n = (int)(idx / (NN / 8));
    int m = mc * 8;

    uint4 hv = *(const uint4*)(g_S + ((size_t)b * NP + n) * NP + m);
    const __half2* h2 = (const __half2*)&hv;
    float4 i0 = *(const float4*)&g_colsum[b * NP + m];
    float4 i1 = *(const float4*)&g_colsum[b * NP + m + 4];
    float2 f0 = __half22float2(h2[0]), f1 = __half22float2(h2[1]);
    float2 f2 = __half22float2(h2[2]), f3 = __half22float2(h2[3]);

    float* orow = out + ((size_t)b * NN + n) * NN + m;
    *(float4*)orow       = make_float4(f0.x * i0.x, f0.y * i0.y, f1.x * i0.z, f1.y * i0.w);
    *(float4*)(orow + 4) = make_float4(f2.x * i1.x, f2.y * i1.y, f3.x * i1.z, f3.y * i1.w);
}

// ---------------------------------------------------------------------------
// Two-stream pipeline: gemm(b) on the main stream; invert(b)+norm(b) on a side
// stream gated by an event, so norm(b) overlaps gemm(b+1). Streams/events are
// created once on the first (uncaptured) call; the captured calls only record
// launches + event dependencies (standard cross-stream graph-capture pattern).
// ---------------------------------------------------------------------------
extern "C" void kernel_launch(void* const* d_in, const int* in_sizes, int n_in,
                              void* d_out, int out_size) {
    const float* mk = (const float*)d_in[0];
    const float* qk = (const float*)d_in[1];
    float* out = (float*)d_out;

    static cudaStream_t s1 = nullptr;
    static cudaEvent_t evG[B_], evJoin;
    static bool inited = false;
    if (!inited) {
        cudaStreamCreateWithFlags(&s1, cudaStreamNonBlocking);
        for (int b = 0; b < B_; ++b)
            cudaEventCreateWithFlags(&evG[b], cudaEventDisableTiming);
        cudaEventCreateWithFlags(&evJoin, cudaEventDisableTiming);
        cudaFuncSetAttribute(gemm_pass1,
                             cudaFuncAttributeMaxDynamicSharedMemorySize, SMEM_P1);
        inited = true;
    }

    dim3 cg(NP / 128, B_, 2);
    conv_kernel<<<cg, 256>>>(mk, qk);

    const unsigned normBlocks = (unsigned)(((size_t)NN * (NN / 8) + 255) / 256);
    dim3 gg(32, 32);
    for (int b = 0; b < B_; ++b) {
        gemm_pass1<<<gg, 256, SMEM_P1>>>(b);
        cudaEventRecord(evG[b], 0);
        cudaStreamWaitEvent(s1, evG[b], 0);
        invert_kernel<<<(NP + 255) / 256, 256, 0, s1>>>(b);
        norm_kernel<<<normBlocks, 256, 0, s1>>>(out, b);
    }
    cudaEventRecord(evJoin, s1);
    cudaStreamWaitEvent(0, evJoin, 0);
}

// round 14
// speedup vs baseline: 1.6150x; 1.1006x over previous
#include <cuda_runtime.h>
#include <cuda_fp16.h>
#include <cstdint>

#define B_   4
#define CK   64
#define NN   4032
#define MM   4032
#define NP   4096
#define KH   192            // fp16 split K: A=[hi|lo|hi], B=[hi|hi|lo]
#define SPITCH 400          // smem row pitch in BYTES (odd multiple of 16B)

// ---- device scratch (allocation-free rule) ----
__device__ __align__(16) __half g_hA[(size_t)B_ * NP * KH];   // mk split, K-major
__device__ __align__(16) __half g_hB[(size_t)B_ * NP * KH];   // qk split, K-major
__device__ __align__(16) __half g_S [(size_t)B_ * NP * NP];   // unnormalized p (fp16)
__device__ float g_msq8  [B_ * NP];   // ||mk_n||^2 / 8
__device__ float g_colsum[B_ * NP];   // colsum -> inverted in place

__device__ __forceinline__ uint32_t smem_u32(const void* p) {
    return (uint32_t)__cvta_generic_to_shared(p);
}
__device__ __forceinline__ void ldsm_x4(uint32_t& r0, uint32_t& r1,
                                        uint32_t& r2, uint32_t& r3, uint32_t a) {
    asm volatile("ldmatrix.sync.aligned.m8n8.x4.shared.b16 {%0,%1,%2,%3}, [%4];"
                 : "=r"(r0), "=r"(r1), "=r"(r2), "=r"(r3) : "r"(a));
}
__device__ __forceinline__ void mma16816(float* d, const uint32_t* a,
                                         uint32_t b0, uint32_t b1) {
    asm volatile("mma.sync.aligned.m16n8k16.row.col.f32.f16.f16.f32 "
                 "{%0,%1,%2,%3}, {%4,%5,%6,%7}, {%8,%9}, {%0,%1,%2,%3};"
                 : "+f"(d[0]), "+f"(d[1]), "+f"(d[2]), "+f"(d[3])
                 : "r"(a[0]), "r"(a[1]), "r"(a[2]), "r"(a[3]), "r"(b0), "r"(b1));
}
__device__ __forceinline__ void cp16(uint32_t dst, const void* src) {
    asm volatile("cp.async.cg.shared.global [%0], [%1], 16;"
                 :: "r"(dst), "l"(src) : "memory");
}

// ---------------------------------------------------------------------------
// Convert: fp32 -> fp16 hi/lo split, K-major padded scratch; msq/8; zero colsum.
// grid (NP/128, B_, 2): z=0 mk->g_hA (hi|lo|hi), z=1 qk->g_hB (hi|hi|lo).
// ---------------------------------------------------------------------------
__global__ __launch_bounds__(256) void conv_kernel(const float* __restrict__ mk,
                                                   const float* __restrict__ qk) {
    __shared__ float s[64][129];
    const int z = blockIdx.z, b = blockIdx.y, n0 = blockIdx.x * 128;
    const int tid = threadIdx.x;
    const float* src = (z ? qk : mk) + (size_t)b * CK * NN;

    for (int idx = tid; idx < 64 * 128; idx += 256) {
        int c = idx >> 7, n = idx & 127;
        s[c][n] = (n0 + n < NN) ? src[(size_t)c * NN + n0 + n] : 0.f;
    }
    __syncthreads();

    if (z == 0 && tid < 128) {
        float acc = 0.f;
        #pragma unroll
        for (int c = 0; c < 64; ++c) acc += s[c][tid] * s[c][tid];
        g_msq8  [b * NP + n0 + tid] = 0.125f * acc;
        g_colsum[b * NP + n0 + tid] = 0.f;
    }

    __half2* dst = (__half2*)((z ? g_hB : g_hA) + ((size_t)b * NP + n0) * KH);
    for (int idx = tid; idx < 128 * 96; idx += 256) {
        int n = idx / 96, w = idx - n * 96;
        int seg = w >> 5;
        int c = (2 * w) & 63;
        bool want_lo = z ? (seg == 2) : (seg == 1);
        float x0 = s[c][n], x1 = s[c + 1][n];
        __half h0 = __float2half_rn(x0), h1 = __float2half_rn(x1);
        if (want_lo) {
            h0 = __float2half_rn(x0 - __half2float(h0));
            h1 = __float2half_rn(x1 - __half2float(h1));
        }
        dst[(size_t)n * 96 + w] = __halves2half2(h0, h1);
    }
}

// ---------------------------------------------------------------------------
// GEMM pass: 128(n) x 96(m) CTA tile, K=192, 384 threads / 12 warps,
// warp tile 32x32 -> 32 accum regs/thread -> 2 CTAs/SM -> 6 warps/SMSP.
// 96 | 4032 so no m-guards anywhere. Fused exp + fp16 p-store + colsum.
// ---------------------------------------------------------------------------
#define TMV 128
#define TNV 96
#define SM_A 0
#define SM_B (TMV * SPITCH)               // 51200
#define SMEM_P1 (SM_B + TNV * SPITCH)     // 89600

__global__ __launch_bounds__(384, 2) void gemm_pass1() {
    extern __shared__ __align__(16) char smem[];
    __shared__ float colred[TNV];
    const int tid = threadIdx.x;
    const int m0 = blockIdx.x * TNV, n0 = blockIdx.y * TMV, b = blockIdx.z;
    const int w = tid >> 5, lane = tid & 31;
    const int wm = w & 3, wn = w >> 2;    // wm: 4 row groups, wn: 3 col groups
    const uint32_t sbase = smem_u32(smem);

    if (tid < TNV) colred[tid] = 0.f;

    // cp.async staging: 3 K-chunks of 64 halves (8 x 16B per row per chunk)
    {
        const uint4* gA = (const uint4*)(g_hA + ((size_t)b * NP + n0) * KH);
        const uint4* gB = (const uint4*)(g_hB + ((size_t)b * NP + m0) * KH);
        const int r = tid >> 3, j = tid & 7;          // r: 0..47, j: 0..7
        #pragma unroll
        for (int c = 0; c < 3; ++c) {
            const int jj = 8 * c + j;
            #pragma unroll
            for (int i = 0; i < 3; ++i) {             // A rows r, r+48, r+96
                int rr = r + i * 48;
                if (rr < TMV)
                    cp16(sbase + SM_A + rr * SPITCH + jj * 16,
                         gA + (size_t)rr * 24 + jj);
            }
            #pragma unroll
            for (int i = 0; i < 2; ++i) {             // B rows r, r+48 (96 exact)
                int rr = r + i * 48;
                cp16(sbase + SM_B + rr * SPITCH + jj * 16,
                     gB + (size_t)rr * 24 + jj);
            }
            asm volatile("cp.async.commit_group;" ::: "memory");
        }
    }

    float d[2][4][4];
    #pragma unroll
    for (int i = 0; i < 2; ++i)
        #pragma unroll
        for (int j = 0; j < 4; ++j)
            #pragma unroll
            for (int k = 0; k < 4; ++k) d[i][j][k] = 0.f;

    const uint32_t aAddr = sbase + SM_A +
        (wm * 32 + (lane & 15)) * SPITCH + ((lane >> 4) << 4);
    const uint32_t bAddr = sbase + SM_B +
        (wn * 32 + (lane & 7) + ((lane >> 4) << 3)) * SPITCH + (((lane >> 3) & 1) << 4);

    #pragma unroll
    for (int c = 0; c < 3; ++c) {
        if (c == 0)      asm volatile("cp.async.wait_group 2;" ::: "memory");
        else if (c == 1) asm volatile("cp.async.wait_group 1;" ::: "memory");
        else             asm volatile("cp.async.wait_group 0;" ::: "memory");
        __syncthreads();

        #pragma unroll
        for (int k4 = 0; k4 < 4; ++k4) {
            const int kb = (c * 4 + k4) * 32;
            uint32_t a[2][4], bf[2][4];
            #pragma unroll
            for (int mi = 0; mi < 2; ++mi)
                ldsm_x4(a[mi][0], a[mi][1], a[mi][2], a[mi][3],
                        aAddr + kb + mi * 16 * SPITCH);
            #pragma unroll
            for (int p = 0; p < 2; ++p)
                ldsm_x4(bf[p][0], bf[p][1], bf[p][2], bf[p][3],
                        bAddr + kb + p * 16 * SPITCH);
            #pragma unroll
            for (int mi = 0; mi < 2; ++mi)
                #pragma unroll
                for (int p = 0; p < 2; ++p) {
                    mma16816(d[mi][2 * p],     a[mi], bf[p][0], bf[p][1]);
                    mma16816(d[mi][2 * p + 1], a[mi], bf[p][2], bf[p][3]);
                }
        }
    }

    // ---- epilogue: exp, p-store (fp16), column sums ----
    const int g = lane >> 2, t4 = lane & 3;
    float q[2][2]; bool v[2][2];
    #pragma unroll
    for (int mi = 0; mi < 2; ++mi) {
        int r0 = n0 + wm * 32 + mi * 16 + g;
        q[mi][0] = g_msq8[b * NP + r0];
        q[mi][1] = g_msq8[b * NP + r0 + 8];
        v[mi][0] = r0 < NN; v[mi][1] = r0 + 8 < NN;
    }
    const size_t sb = (size_t)b * NP * NP;

    #pragma unroll
    for (int nj = 0; nj < 4; ++nj) {
        float cs0 = 0.f, cs1 = 0.f;
        const int mcol = m0 + wn * 32 + nj * 8 + 2 * t4;   // always < MM (96|4032)
        #pragma unroll
        for (int mi = 0; mi < 2; ++mi) {
            int r0 = n0 + wm * 32 + mi * 16 + g;
            float p00 = __expf(d[mi][nj][0] * 0.25f - q[mi][0]);
            float p01 = __expf(d[mi][nj][1] * 0.25f - q[mi][0]);
            float p10 = __expf(d[mi][nj][2] * 0.25f - q[mi][1]);
            float p11 = __expf(d[mi][nj][3] * 0.25f - q[mi][1]);
            *(__half2*)(g_S + sb + (size_t)r0 * NP + mcol)       = __floats2half2_rn(p00, p01);
            *(__half2*)(g_S + sb + (size_t)(r0 + 8) * NP + mcol) = __floats2half2_rn(p10, p11);
            if (v[mi][0]) { cs0 += p00; cs1 += p01; }
            if (v[mi][1]) { cs0 += p10; cs1 += p11; }
        }
        #pragma unroll
        for (int off = 4; off <= 16; off <<= 1) {
            cs0 += __shfl_xor_sync(0xffffffffu, cs0, off);
            cs1 += __shfl_xor_sync(0xffffffffu, cs1, off);
        }
        if (g == 0) {
            atomicAdd(&colred[wn * 32 + nj * 8 + 2 * t4],     cs0);
            atomicAdd(&colred[wn * 32 + nj * 8 + 2 * t4 + 1], cs1);
        }
    }
    __syncthreads();
    if (tid < TNV)
        atomicAdd(&g_colsum[b * NP + m0 + tid], colred[tid]);
}

// ---------------------------------------------------------------------------
__global__ void invert_kernel() {
    int i = blockIdx.x * 256 + threadIdx.x;
    if (i < B_ * NP) g_colsum[i] = __frcp_rn(g_colsum[i]);
}

// ---------------------------------------------------------------------------
// Norm: out = fp16->fp32(g_S) * inv_colsum[b][m].  R6/R8-proven shape:
// 8 cols/thread, plain loads/stores, 31752 blocks. Do not reshape (R7 lesson).
// ---------------------------------------------------------------------------
__global__ __launch_bounds__(256) void norm_kernel(float* __restrict__ out) {
    size_t idx = (size_t)blockIdx.x * 256 + threadIdx.x;
    const size_t total = (size_t)B_ * NN * (NN / 8);
    if (idx >= total) return;
    int mc = (int)(idx % (NN / 8));
    size_t bn = idx / (NN / 8);
    int n = (int)(bn % NN);
    int b = (int)(bn / NN);
    int m = mc * 8;

    uint4 hv = *(const uint4*)(g_S + ((size_t)b * NP + n) * NP + m);
    const __half2* h2 = (const __half2*)&hv;
    float4 i0 = *(const float4*)&g_colsum[b * NP + m];
    float4 i1 = *(const float4*)&g_colsum[b * NP + m + 4];
    float2 f0 = __half22float2(h2[0]), f1 = __half22float2(h2[1]);
    float2 f2 = __half22float2(h2[2]), f3 = __half22float2(h2[3]);

    float* orow = out + ((size_t)b * NN + n) * NN + m;
    *(float4*)orow       = make_float4(f0.x * i0.x, f0.y * i0.y, f1.x * i0.z, f1.y * i0.w);
    *(float4*)(orow + 4) = make_float4(f2.x * i1.x, f2.y * i1.y, f3.x * i1.z, f3.y * i1.w);
}

// ---------------------------------------------------------------------------
extern "C" void kernel_launch(void* const* d_in, const int* in_sizes, int n_in,
                              void* d_out, int out_size) {
    const float* mk = (const float*)d_in[0];
    const float* qk = (const float*)d_in[1];
    float* out = (float*)d_out;

    cudaFuncSetAttribute(gemm_pass1,
                         cudaFuncAttributeMaxDynamicSharedMemorySize, SMEM_P1);

    dim3 cg(NP / 128, B_, 2);
    conv_kernel<<<cg, 256>>>(mk, qk);

    dim3 gg(MM / TNV, NP / TMV, B_);      // 42 x 32 x 4 = 5376 CTAs
    gemm_pass1<<<gg, 384, SMEM_P1>>>();

    invert_kernel<<<(B_ * NP + 255) / 256, 256>>>();

    size_t total = (size_t)B_ * NN * (NN / 8);
    norm_kernel<<<(unsigned)((total + 255) / 256), 256>>>(out);
}

// round 15
// speedup vs baseline: 1.8611x; 1.1524x over previous
#include <cuda_runtime.h>
#include <cuda_fp16.h>
#include <cstdint>

#define B_   4
#define CK   64
#define NN   4032
#define MM   4032
#define NP   4096
#define KH   128            // fp16 split K: A=[hi|lo], B=[hi|hi] (hi*lo term dropped)
#define SPITCH 272          // smem row pitch BYTES (17*16: odd multiple of 16 -> conflict-free)
#define L2E  1.44269504f

// ---- device scratch (allocation-free rule) ----
__device__ __align__(16) __half g_hA[(size_t)B_ * NP * KH];   // mk split, K-major
__device__ __align__(16) __half g_hB[(size_t)B_ * NP * KH];   // qk split, K-major
__device__ __align__(16) __half g_S [(size_t)B_ * NP * NP];   // unnormalized p (fp16)
__device__ float g_msq8l [B_ * NP];   // ||mk_n||^2 / 8 * log2(e)
__device__ float g_colsum[B_ * NP];   // colsum -> inverted in place

__device__ __forceinline__ uint32_t smem_u32(const void* p) {
    return (uint32_t)__cvta_generic_to_shared(p);
}
__device__ __forceinline__ void ldsm_x4(uint32_t& r0, uint32_t& r1,
                                        uint32_t& r2, uint32_t& r3, uint32_t a) {
    asm volatile("ldmatrix.sync.aligned.m8n8.x4.shared.b16 {%0,%1,%2,%3}, [%4];"
                 : "=r"(r0), "=r"(r1), "=r"(r2), "=r"(r3) : "r"(a));
}
__device__ __forceinline__ void mma16816(float* d, const uint32_t* a,
                                         uint32_t b0, uint32_t b1) {
    asm volatile("mma.sync.aligned.m16n8k16.row.col.f32.f16.f16.f32 "
                 "{%0,%1,%2,%3}, {%4,%5,%6,%7}, {%8,%9}, {%0,%1,%2,%3};"
                 : "+f"(d[0]), "+f"(d[1]), "+f"(d[2]), "+f"(d[3])
                 : "r"(a[0]), "r"(a[1]), "r"(a[2]), "r"(a[3]), "r"(b0), "r"(b1));
}
__device__ __forceinline__ void cp16(uint32_t dst, const void* src) {
    asm volatile("cp.async.cg.shared.global [%0], [%1], 16;"
                 :: "r"(dst), "l"(src) : "memory");
}

// ---------------------------------------------------------------------------
// Convert: fp32 -> fp16 hi/lo split, K-major padded scratch; msq8*log2e; zero
// colsum. grid (NP/128, B_, 2): z=0 mk->g_hA [hi|lo], z=1 qk->g_hB [hi|hi].
// ---------------------------------------------------------------------------
__global__ __launch_bounds__(256) void conv_kernel(const float* __restrict__ mk,
                                                   const float* __restrict__ qk) {
    __shared__ float s[64][129];
    const int z = blockIdx.z, b = blockIdx.y, n0 = blockIdx.x * 128;
    const int tid = threadIdx.x;
    const float* src = (z ? qk : mk) + (size_t)b * CK * NN;

    for (int idx = tid; idx < 64 * 128; idx += 256) {
        int c = idx >> 7, n = idx & 127;
        s[c][n] = (n0 + n < NN) ? src[(size_t)c * NN + n0 + n] : 0.f;
    }
    __syncthreads();

    if (z == 0 && tid < 128) {
        float acc = 0.f;
        #pragma unroll
        for (int c = 0; c < 64; ++c) acc += s[c][tid] * s[c][tid];
        g_msq8l [b * NP + n0 + tid] = 0.125f * L2E * acc;
        g_colsum[b * NP + n0 + tid] = 0.f;
    }

    __half2* dst = (__half2*)((z ? g_hB : g_hA) + ((size_t)b * NP + n0) * KH);
    for (int idx = tid; idx < 128 * 64; idx += 256) {
        int n = idx >> 6, w = idx & 63;
        int seg = w >> 5;                 // 0,1 (64 halves each)
        int c = (2 * w) & 63;
        bool want_lo = (z == 0) && (seg == 1);   // A: [hi|lo], B: [hi|hi]
        float x0 = s[c][n], x1 = s[c + 1][n];
        __half h0 = __float2half_rn(x0), h1 = __float2half_rn(x1);
        if (want_lo) {
            h0 = __float2half_rn(x0 - __half2float(h0));
            h1 = __float2half_rn(x1 - __half2float(h1));
        }
        dst[(size_t)n * 64 + w] = __halves2half2(h0, h1);
    }
}

// ---------------------------------------------------------------------------
// GEMM pass: 128(n) x 96(m) CTA tile, K=128, 384 threads / 12 warps,
// warp tile 32x32, 2 K-chunks via cp.async. 96 | 4032 -> no m-guards.
// Fused exp2 + fp16 p-store + colsum.
// ---------------------------------------------------------------------------
#define TMV 128
#define TNV 96
#define SM_A 0
#define SM_B (TMV * SPITCH)               // 34816
#define SMEM_P1 (SM_B + TNV * SPITCH)     // 60928

__global__ __launch_bounds__(384, 2) void gemm_pass1() {
    extern __shared__ __align__(16) char smem[];
    __shared__ float colred[TNV];
    const int tid = threadIdx.x;
    const int m0 = blockIdx.x * TNV, n0 = blockIdx.y * TMV, b = blockIdx.z;
    const int w = tid >> 5, lane = tid & 31;
    const int wm = w & 3, wn = w >> 2;    // 4 row groups x 3 col groups
    const uint32_t sbase = smem_u32(smem);

    if (tid < TNV) colred[tid] = 0.f;

    // cp.async staging: 2 K-chunks of 64 halves (8 x 16B per row per chunk)
    {
        const uint4* gA = (const uint4*)(g_hA + ((size_t)b * NP + n0) * KH);
        const uint4* gB = (const uint4*)(g_hB + ((size_t)b * NP + m0) * KH);
        const int r = tid >> 3, j = tid & 7;          // r: 0..47, j: 0..7
        #pragma unroll
        for (int c = 0; c < 2; ++c) {
            const int jj = 8 * c + j;                 // uint4 index (row = 16 uint4)
            #pragma unroll
            for (int i = 0; i < 3; ++i) {             // A rows r, r+48, r+96
                int rr = r + i * 48;
                if (rr < TMV)
                    cp16(sbase + SM_A + rr * SPITCH + jj * 16,
                         gA + (size_t)rr * 16 + jj);
            }
            #pragma unroll
            for (int i = 0; i < 2; ++i) {             // B rows r, r+48 (96 exact)
                int rr = r + i * 48;
                cp16(sbase + SM_B + rr * SPITCH + jj * 16,
                     gB + (size_t)rr * 16 + jj);
            }
            asm volatile("cp.async.commit_group;" ::: "memory");
        }
    }

    float d[2][4][4];
    #pragma unroll
    for (int i = 0; i < 2; ++i)
        #pragma unroll
        for (int j = 0; j < 4; ++j)
            #pragma unroll
            for (int k = 0; k < 4; ++k) d[i][j][k] = 0.f;

    const uint32_t aAddr = sbase + SM_A +
        (wm * 32 + (lane & 15)) * SPITCH + ((lane >> 4) << 4);
    const uint32_t bAddr = sbase + SM_B +
        (wn * 32 + (lane & 7) + ((lane >> 4) << 3)) * SPITCH + (((lane >> 3) & 1) << 4);

    #pragma unroll
    for (int c = 0; c < 2; ++c) {
        if (c == 0) asm volatile("cp.async.wait_group 1;" ::: "memory");
        else        asm volatile("cp.async.wait_group 0;" ::: "memory");
        __syncthreads();

        #pragma unroll
        for (int k4 = 0; k4 < 4; ++k4) {
            const int kb = (c * 4 + k4) * 32;         // byte offset within row
            uint32_t a[2][4], bf[2][4];
            #pragma unroll
            for (int mi = 0; mi < 2; ++mi)
                ldsm_x4(a[mi][0], a[mi][1], a[mi][2], a[mi][3],
                        aAddr + kb + mi * 16 * SPITCH);
            #pragma unroll
            for (int p = 0; p < 2; ++p)
                ldsm_x4(bf[p][0], bf[p][1], bf[p][2], bf[p][3],
                        bAddr + kb + p * 16 * SPITCH);
            #pragma unroll
            for (int mi = 0; mi < 2; ++mi)
                #pragma unroll
                for (int p = 0; p < 2; ++p) {
                    mma16816(d[mi][2 * p],     a[mi], bf[p][0], bf[p][1]);
                    mma16816(d[mi][2 * p + 1], a[mi], bf[p][2], bf[p][3]);
                }
        }
    }

    // ---- epilogue: exp2, p-store (fp16), column sums ----
    const int g = lane >> 2, t4 = lane & 3;
    float q[2][2]; bool v[2][2];
    #pragma unroll
    for (int mi = 0; mi < 2; ++mi) {
        int r0 = n0 + wm * 32 + mi * 16 + g;
        q[mi][0] = g_msq8l[b * NP + r0];
        q[mi][1] = g_msq8l[b * NP + r0 + 8];
        v[mi][0] = r0 < NN; v[mi][1] = r0 + 8 < NN;
    }
    const size_t sb = (size_t)b * NP * NP;
    const float SC = 0.25f * L2E;                      // logit2 = d*SC - msq8l

    #pragma unroll
    for (int nj = 0; nj < 4; ++nj) {
        float cs0 = 0.f, cs1 = 0.f;
        const int mcol = m0 + wn * 32 + nj * 8 + 2 * t4;
        #pragma unroll
        for (int mi = 0; mi < 2; ++mi) {
            int r0 = n0 + wm * 32 + mi * 16 + g;
            float p00 = exp2f(fmaf(d[mi][nj][0], SC, -q[mi][0]));
            float p01 = exp2f(fmaf(d[mi][nj][1], SC, -q[mi][0]));
            float p10 = exp2f(fmaf(d[mi][nj][2], SC, -q[mi][1]));
            float p11 = exp2f(fmaf(d[mi][nj][3], SC, -q[mi][1]));
            *(__half2*)(g_S + sb + (size_t)r0 * NP + mcol)       = __floats2half2_rn(p00, p01);
            *(__half2*)(g_S + sb + (size_t)(r0 + 8) * NP + mcol) = __floats2half2_rn(p10, p11);
            if (v[mi][0]) { cs0 += p00; cs1 += p01; }
            if (v[mi][1]) { cs0 += p10; cs1 += p11; }
        }
        #pragma unroll
        for (int off = 4; off <= 16; off <<= 1) {
            cs0 += __shfl_xor_sync(0xffffffffu, cs0, off);
            cs1 += __shfl_xor_sync(0xffffffffu, cs1, off);
        }
        if (g == 0) {
            atomicAdd(&colred[wn * 32 + nj * 8 + 2 * t4],     cs0);
            atomicAdd(&colred[wn * 32 + nj * 8 + 2 * t4 + 1], cs1);
        }
    }
    __syncthreads();
    if (tid < TNV)
        atomicAdd(&g_colsum[b * NP + m0 + tid], colred[tid]);
}

// ---------------------------------------------------------------------------
__global__ void invert_kernel() {
    int i = blockIdx.x * 256 + threadIdx.x;
    if (i < B_ * NP) g_colsum[i] = __frcp_rn(g_colsum[i]);
}

// ---------------------------------------------------------------------------
// Norm: out = fp16->fp32(g_S) * inv_colsum[b][m].  R6/R8-proven shape:
// 8 cols/thread, plain loads/stores, 31752 blocks. Do not reshape (R7 lesson).
// ---------------------------------------------------------------------------
__global__ __launch_bounds__(256) void norm_kernel(float* __restrict__ out) {
    size_t idx = (size_t)blockIdx.x * 256 + threadIdx.x;
    const size_t total = (size_t)B_ * NN * (NN / 8);
    if (idx >= total) return;
    int mc = (int)(idx % (NN / 8));
    size_t bn = idx / (NN / 8);
    int n = (int)(bn % NN);
    int b = (int)(bn / NN);
    int m = mc * 8;

    uint4 hv = *(const uint4*)(g_S + ((size_t)b * NP + n) * NP + m);
    const __half2* h2 = (const __half2*)&hv;
    float4 i0 = *(const float4*)&g_colsum[b * NP + m];
    float4 i1 = *(const float4*)&g_colsum[b * NP + m + 4];
    float2 f0 = __half22float2(h2[0]), f1 = __half22float2(h2[1]);
    float2 f2 = __half22float2(h2[2]), f3 = __half22float2(h2[3]);

    float* orow = out + ((size_t)b * NN + n) * NN + m;
    *(float4*)orow       = make_float4(f0.x * i0.x, f0.y * i0.y, f1.x * i0.z, f1.y * i0.w);
    *(float4*)(orow + 4) = make_float4(f2.x * i1.x, f2.y * i1.y, f3.x * i1.z, f3.y * i1.w);
}

// ---------------------------------------------------------------------------
extern "C" void kernel_launch(void* const* d_in, const int* in_sizes, int n_in,
                              void* d_out, int out_size) {
    const float* mk = (const float*)d_in[0];
    const float* qk = (const float*)d_in[1];
    float* out = (float*)d_out;

    cudaFuncSetAttribute(gemm_pass1,
                         cudaFuncAttributeMaxDynamicSharedMemorySize, SMEM_P1);

    dim3 cg(NP / 128, B_, 2);
    conv_kernel<<<cg, 256>>>(mk, qk);

    dim3 gg(MM / TNV, NP / TMV, B_);      // 42 x 32 x 4 = 5376 CTAs
    gemm_pass1<<<gg, 384, SMEM_P1>>>();

    invert_kernel<<<(B_ * NP + 255) / 256, 256>>>();

    size_t total = (size_t)B_ * NN * (NN / 8);
    norm_kernel<<<(unsigned)((total + 255) / 256), 256>>>(out);
}

// round 17
// speedup vs baseline: 2.0586x; 1.1061x over previous
#include <cuda_runtime.h>
#include <cuda_fp16.h>
#include <cstdint>

#define B_   4
#define CK   64
#define NN   4032
#define MM   4032
#define NP   4096
#define KH   64             // pure fp16, no split (calibrated err ~5.3e-4 < 1e-3)
#define SPITCH 144          // smem row pitch BYTES (9*16: odd multiple of 16 -> conflict-free)
#define L2E  1.44269504f

// ---- device scratch (allocation-free rule) ----
__device__ __align__(16) __half g_hA[(size_t)B_ * NP * KH];   // mk fp16, K-major
__device__ __align__(16) __half g_hB[(size_t)B_ * NP * KH];   // qk fp16, K-major
__device__ __align__(16) __half g_S [(size_t)B_ * NP * NP];   // unnormalized p (fp16)
__device__ float g_msq8l [B_ * NP];   // ||mk_n||^2 / 8 * log2(e)
__device__ float g_colsum[B_ * NP];   // colsum -> inverted in place

__device__ __forceinline__ uint32_t smem_u32(const void* p) {
    return (uint32_t)__cvta_generic_to_shared(p);
}
__device__ __forceinline__ void ldsm_x4(uint32_t& r0, uint32_t& r1,
                                        uint32_t& r2, uint32_t& r3, uint32_t a) {
    asm volatile("ldmatrix.sync.aligned.m8n8.x4.shared.b16 {%0,%1,%2,%3}, [%4];"
                 : "=r"(r0), "=r"(r1), "=r"(r2), "=r"(r3) : "r"(a));
}
__device__ __forceinline__ void mma16816(float* d, const uint32_t* a,
                                         uint32_t b0, uint32_t b1) {
    asm volatile("mma.sync.aligned.m16n8k16.row.col.f32.f16.f16.f32 "
                 "{%0,%1,%2,%3}, {%4,%5,%6,%7}, {%8,%9}, {%0,%1,%2,%3};"
                 : "+f"(d[0]), "+f"(d[1]), "+f"(d[2]), "+f"(d[3])
                 : "r"(a[0]), "r"(a[1]), "r"(a[2]), "r"(a[3]), "r"(b0), "r"(b1));
}
__device__ __forceinline__ void cp16(uint32_t dst, const void* src) {
    asm volatile("cp.async.cg.shared.global [%0], [%1], 16;"
                 :: "r"(dst), "l"(src) : "memory");
}

// ---------------------------------------------------------------------------
// Convert: fp32 -> fp16 (round-nearest), K-major padded scratch; msq8*log2e;
// zero colsum. grid (NP/128, B_, 2): z=0 mk->g_hA, z=1 qk->g_hB.
// ---------------------------------------------------------------------------
__global__ __launch_bounds__(256) void conv_kernel(const float* __restrict__ mk,
                                                   const float* __restrict__ qk) {
    __shared__ float s[64][129];
    const int z = blockIdx.z, b = blockIdx.y, n0 = blockIdx.x * 128;
    const int tid = threadIdx.x;
    const float* src = (z ? qk : mk) + (size_t)b * CK * NN;

    for (int idx = tid; idx < 64 * 128; idx += 256) {
        int c = idx >> 7, n = idx & 127;
        s[c][n] = (n0 + n < NN) ? src[(size_t)c * NN + n0 + n] : 0.f;
    }
    __syncthreads();

    if (z == 0 && tid < 128) {
        float acc = 0.f;
        #pragma unroll
        for (int c = 0; c < 64; ++c) acc += s[c][tid] * s[c][tid];
        g_msq8l [b * NP + n0 + tid] = 0.125f * L2E * acc;
        g_colsum[b * NP + n0 + tid] = 0.f;
    }

    __half2* dst = (__half2*)((z ? g_hB : g_hA) + ((size_t)b * NP + n0) * KH);
    for (int idx = tid; idx < 128 * 32; idx += 256) {
        int n = idx >> 5, w = idx & 31;             // 32 half2 per row
        int c = 2 * w;
        dst[(size_t)n * 32 + w] =
            __floats2half2_rn(s[c][n], s[c + 1][n]);
    }
}

// ---------------------------------------------------------------------------
// GEMM pass: 128(n) x 96(m) CTA tile, K=64 pure fp16, 384 threads / 12 warps,
// warp tile 32x32, single cp.async chunk. 96 | 4032 -> no m-guards.
// Fused exp2 + fp16 p-store + colsum.
// ---------------------------------------------------------------------------
#define TMV 128
#define TNV 96
#define SM_A 0
#define SM_B (TMV * SPITCH)               // 18432
#define SMEM_P1 (SM_B + TNV * SPITCH)     // 32256

__global__ __launch_bounds__(384, 2) void gemm_pass1() {
    extern __shared__ __align__(16) char smem[];
    __shared__ float colred[TNV];
    const int tid = threadIdx.x;
    const int m0 = blockIdx.x * TNV, n0 = blockIdx.y * TMV, b = blockIdx.z;
    const int w = tid >> 5, lane = tid & 31;
    const int wm = w & 3, wn = w >> 2;    // 4 row groups x 3 col groups
    const uint32_t sbase = smem_u32(smem);

    if (tid < TNV) colred[tid] = 0.f;

    // cp.async staging: one chunk, 8 x 16B per row (K=64 halves = 128B).
    {
        const uint4* gA = (const uint4*)(g_hA + ((size_t)b * NP + n0) * KH);
        const uint4* gB = (const uint4*)(g_hB + ((size_t)b * NP + m0) * KH);
        const int r = tid >> 3, j = tid & 7;          // r: 0..47, j: 0..7
        #pragma unroll
        for (int i = 0; i < 3; ++i) {                 // A rows r, r+48, r+96
            int rr = r + i * 48;
            if (rr < TMV)
                cp16(sbase + SM_A + rr * SPITCH + j * 16,
                     gA + (size_t)rr * 8 + j);
        }
        #pragma unroll
        for (int i = 0; i < 2; ++i) {                 // B rows r, r+48 (96 exact)
            int rr = r + i * 48;
            cp16(sbase + SM_B + rr * SPITCH + j * 16,
                 gB + (size_t)rr * 8 + j);
        }
        asm volatile("cp.async.commit_group;" ::: "memory");
    }

    float d[2][4][4];
    #pragma unroll
    for (int i = 0; i < 2; ++i)
        #pragma unroll
        for (int j = 0; j < 4; ++j)
            #pragma unroll
            for (int k = 0; k < 4; ++k) d[i][j][k] = 0.f;

    const uint32_t aAddr = sbase + SM_A +
        (wm * 32 + (lane & 15)) * SPITCH + ((lane >> 4) << 4);
    const uint32_t bAddr = sbase + SM_B +
        (wn * 32 + (lane & 7) + ((lane >> 4) << 3)) * SPITCH + (((lane >> 3) & 1) << 4);

    asm volatile("cp.async.wait_group 0;" ::: "memory");
    __syncthreads();

    #pragma unroll
    for (int k4 = 0; k4 < 4; ++k4) {
        const int kb = k4 * 32;                       // byte offset within row
        uint32_t a[2][4], bf[2][4];
        #pragma unroll
        for (int mi = 0; mi < 2; ++mi)
            ldsm_x4(a[mi][0], a[mi][1], a[mi][2], a[mi][3],
                    aAddr + kb + mi * 16 * SPITCH);
        #pragma unroll
        for (int p = 0; p < 2; ++p)
            ldsm_x4(bf[p][0], bf[p][1], bf[p][2], bf[p][3],
                    bAddr + kb + p * 16 * SPITCH);
        #pragma unroll
        for (int mi = 0; mi < 2; ++mi)
            #pragma unroll
            for (int p = 0; p < 2; ++p) {
                mma16816(d[mi][2 * p],     a[mi], bf[p][0], bf[p][1]);
                mma16816(d[mi][2 * p + 1], a[mi], bf[p][2], bf[p][3]);
            }
    }

    // ---- epilogue: exp2, p-store (fp16), column sums ----
    const int g = lane >> 2, t4 = lane & 3;
    float q[2][2]; bool v[2][2];
    #pragma unroll
    for (int mi = 0; mi < 2; ++mi) {
        int r0 = n0 + wm * 32 + mi * 16 + g;
        q[mi][0] = g_msq8l[b * NP + r0];
        q[mi][1] = g_msq8l[b * NP + r0 + 8];
        v[mi][0] = r0 < NN; v[mi][1] = r0 + 8 < NN;
    }
    const size_t sb = (size_t)b * NP * NP;
    const float SC = 0.25f * L2E;                      // logit2 = d*SC - msq8l

    #pragma unroll
    for (int nj = 0; nj < 4; ++nj) {
        float cs0 = 0.f, cs1 = 0.f;
        const int mcol = m0 + wn * 32 + nj * 8 + 2 * t4;
        #pragma unroll
        for (int mi = 0; mi < 2; ++mi) {
            int r0 = n0 + wm * 32 + mi * 16 + g;
            float p00 = exp2f(fmaf(d[mi][nj][0], SC, -q[mi][0]));
            float p01 = exp2f(fmaf(d[mi][nj][1], SC, -q[mi][0]));
            float p10 = exp2f(fmaf(d[mi][nj][2], SC, -q[mi][1]));
            float p11 = exp2f(fmaf(d[mi][nj][3], SC, -q[mi][1]));
            *(__half2*)(g_S + sb + (size_t)r0 * NP + mcol)       = __floats2half2_rn(p00, p01);
            *(__half2*)(g_S + sb + (size_t)(r0 + 8) * NP + mcol) = __floats2half2_rn(p10, p11);
            if (v[mi][0]) { cs0 += p00; cs1 += p01; }
            if (v[mi][1]) { cs0 += p10; cs1 += p11; }
        }
        #pragma unroll
        for (int off = 4; off <= 16; off <<= 1) {
            cs0 += __shfl_xor_sync(0xffffffffu, cs0, off);
            cs1 += __shfl_xor_sync(0xffffffffu, cs1, off);
        }
        if (g == 0) {
            atomicAdd(&colred[wn * 32 + nj * 8 + 2 * t4],     cs0);
            atomicAdd(&colred[wn * 32 + nj * 8 + 2 * t4 + 1], cs1);
        }
    }
    __syncthreads();
    if (tid < TNV)
        atomicAdd(&g_colsum[b * NP + m0 + tid], colred[tid]);
}

// ---------------------------------------------------------------------------
__global__ void invert_kernel() {
    int i = blockIdx.x * 256 + threadIdx.x;
    if (i < B_ * NP) g_colsum[i] = __frcp_rn(g_colsum[i]);
}

// ---------------------------------------------------------------------------
// Norm: out = fp16->fp32(g_S) * inv_colsum[b][m].  R6/R8-proven shape:
// 8 cols/thread, plain loads/stores, 31752 blocks. Do not reshape (R7 lesson).
// ---------------------------------------------------------------------------
__global__ __launch_bounds__(256) void norm_kernel(float* __restrict__ out) {
    size_t idx = (size_t)blockIdx.x * 256 + threadIdx.x;
    const size_t total = (size_t)B_ * NN * (NN / 8);
    if (idx >= total) return;
    int mc = (int)(idx % (NN / 8));
    size_t bn = idx / (NN / 8);
    int n = (int)(bn % NN);
    int b = (int)(bn / NN);
    int m = mc * 8;

    uint4 hv = *(const uint4*)(g_S + ((size_t)b * NP + n) * NP + m);
    const __half2* h2 = (const __half2*)&hv;
    float4 i0 = *(const float4*)&g_colsum[b * NP + m];
    float4 i1 = *(const float4*)&g_colsum[b * NP + m + 4];
    float2 f0 = __half22float2(h2[0]), f1 = __half22float2(h2[1]);
    float2 f2 = __half22float2(h2[2]), f3 = __half22float2(h2[3]);

    float* orow = out + ((size_t)b * NN + n) * NN + m;
    *(float4*)orow       = make_float4(f0.x * i0.x, f0.y * i0.y, f1.x * i0.z, f1.y * i0.w);
    *(float4*)(orow + 4) = make_float4(f2.x * i1.x, f2.y * i1.y, f3.x * i1.z, f3.y * i1.w);
}

// ---------------------------------------------------------------------------
extern "C" void kernel_launch(void* const* d_in, const int* in_sizes, int n_in,
                              void* d_out, int out_size) {
    const float* mk = (const float*)d_in[0];
    const float* qk = (const float*)d_in[1];
    float* out = (float*)d_out;

    cudaFuncSetAttribute(gemm_pass1,
                         cudaFuncAttributeMaxDynamicSharedMemorySize, SMEM_P1);

    dim3 cg(NP / 128, B_, 2);
    conv_kernel<<<cg, 256>>>(mk, qk);

    dim3 gg(MM / TNV, NP / TMV, B_);      // 42 x 32 x 4 = 5376 CTAs
    gemm_pass1<<<gg, 384, SMEM_P1>>>();

    invert_kernel<<<(B_ * NP + 255) / 256, 256>>>();

    size_t total = (size_t)B_ * NN * (NN / 8);
    norm_kernel<<<(unsigned)((total + 255) / 256), 256>>>(out);
}